// round 7
// baseline (speedup 1.0000x reference)
#include <cuda_runtime.h>
#include <cstdint>

// Fixed problem shapes (from reference setup_inputs).
constexpr int B_   = 2;
constexpr int N_   = 2048;
constexpr int C_   = 1024;
constexpr int H_   = 16;
constexpr int Dh_  = 64;
constexpr int M_ROWS = B_ * N_;     // 4096
constexpr int QKV_N  = 3 * C_;      // 3072

// Scratch (device globals: allocation APIs are forbidden).
__device__ float g_qkv[(size_t)M_ROWS * QKV_N];   // [B*N, 3C]
__device__ float g_ao [(size_t)M_ROWS * C_];      // [B*N, C] attention output (head-concat)
__device__ float g_vsum[B_ * H_ * Dh_];           // per (b,h): sum over n of v

// ---------------------------------------------------------------------------
// GEMM: D[M,Nn] = A[M,K] @ Bw[Nn,K]^T (+ bias). Both operands K-major row-major.
// 128x128 block tile, BK=16, 256 threads, 8x8 per-thread microtile.
// ---------------------------------------------------------------------------
template<bool BIAS>
__global__ __launch_bounds__(256) void sgemm_tn(
    const float* __restrict__ A, const float* __restrict__ Bw,
    const float* __restrict__ bias, float* __restrict__ D,
    int M, int Nn, int K)
{
    constexpr int BM = 128, BN = 128, BK = 16;
    __shared__ float As[BK][BM];
    __shared__ float Bs[BK][BN];

    const int tid = threadIdx.x;
    const int bm = blockIdx.y * BM;
    const int bn = blockIdx.x * BN;
    const int tm = (tid >> 4) << 3;   // 0..120 step 8
    const int tn = (tid & 15) << 3;   // 0..120 step 8

    float acc[8][8] = {};

    for (int k0 = 0; k0 < K; k0 += BK) {
        #pragma unroll
        for (int i = 0; i < 2; i++) {
            int idx = tid + i * 256;          // 0..511
            int row = idx >> 2;               // 0..127
            int kc  = (idx & 3) << 2;         // 0,4,8,12
            float4 av = *reinterpret_cast<const float4*>(
                &A[(size_t)(bm + row) * K + k0 + kc]);
            As[kc+0][row] = av.x; As[kc+1][row] = av.y;
            As[kc+2][row] = av.z; As[kc+3][row] = av.w;
            float4 bv = *reinterpret_cast<const float4*>(
                &Bw[(size_t)(bn + row) * K + k0 + kc]);
            Bs[kc+0][row] = bv.x; Bs[kc+1][row] = bv.y;
            Bs[kc+2][row] = bv.z; Bs[kc+3][row] = bv.w;
        }
        __syncthreads();

        #pragma unroll
        for (int kk = 0; kk < BK; kk++) {
            float a[8], b[8];
            #pragma unroll
            for (int i = 0; i < 8; i++) a[i] = As[kk][tm + i];
            #pragma unroll
            for (int j = 0; j < 8; j++) b[j] = Bs[kk][tn + j];
            #pragma unroll
            for (int i = 0; i < 8; i++)
                #pragma unroll
                for (int j = 0; j < 8; j++)
                    acc[i][j] = fmaf(a[i], b[j], acc[i][j]);
        }
        __syncthreads();
    }

    #pragma unroll
    for (int i = 0; i < 8; i++) {
        #pragma unroll
        for (int j = 0; j < 8; j += 4) {
            float4 o;
            o.x = acc[i][j];   o.y = acc[i][j+1];
            o.z = acc[i][j+2]; o.w = acc[i][j+3];
            if (BIAS) {
                o.x += bias[bn + tn + j];
                o.y += bias[bn + tn + j + 1];
                o.z += bias[bn + tn + j + 2];
                o.w += bias[bn + tn + j + 3];
            }
            *reinterpret_cast<float4*>(
                &D[(size_t)(bm + tm + i) * Nn + bn + tn + j]) = o;
        }
    }
}

// ---------------------------------------------------------------------------
// Vsum[b,h,d] = sum_n v[b,h,n,d], v lives at qkv row offset 2C + h*Dh.
// One block per (b,h): 1024 threads = 16 partials x 64 dims.
// ---------------------------------------------------------------------------
__global__ __launch_bounds__(1024) void vsum_kernel()
{
    const int bh  = blockIdx.x;          // 0..31
    const int tid = threadIdx.x;
    const int d    = tid & 63;
    const int part = tid >> 6;           // 0..15, 128 rows each
    const int b = bh >> 4, h = bh & 15;

    const float* vp = g_qkv + (size_t)(b * N_) * QKV_N + 2 * C_ + h * Dh_ + d;
    const int n0 = part * 128;
    float s0 = 0.f, s1 = 0.f, s2 = 0.f, s3 = 0.f;
    for (int n = 0; n < 128; n += 4) {
        s0 += vp[(size_t)(n0 + n    ) * QKV_N];
        s1 += vp[(size_t)(n0 + n + 1) * QKV_N];
        s2 += vp[(size_t)(n0 + n + 2) * QKV_N];
        s3 += vp[(size_t)(n0 + n + 3) * QKV_N];
    }
    __shared__ float red[1024];
    red[tid] = (s0 + s1) + (s2 + s3);
    __syncthreads();
    if (part == 0) {
        float s = 0.f;
        #pragma unroll
        for (int p = 0; p < 16; p++) s += red[p * 64 + d];
        g_vsum[bh * 64 + d] = s;
    }
}

// ---------------------------------------------------------------------------
// Banded attention with exact out-of-band (1e-9 logit) correction.
// Block = 64 rows of one (b,h). 8 warps; each warp owns one row at a time.
// ---------------------------------------------------------------------------
__global__ __launch_bounds__(256) void attn_kernel(const int* __restrict__ epoch)
{
    constexpr int RB = 64, HALO = 20, TR = RB + 2 * HALO, LD = 65;
    const int b  = blockIdx.z;
    const int h  = blockIdx.y;
    const int n0 = blockIdx.x * RB;
    const int w  = (*epoch < 15) ? 16 : 20;   // faithful to reference branch

    __shared__ float qs[RB][LD];
    __shared__ float ks[TR][LD];
    __shared__ float ew[8][64];
    __shared__ float vsum_s[64];

    const int tid = threadIdx.x;
    if (tid < 64) vsum_s[tid] = g_vsum[(b * H_ + h) * 64 + tid];

    const int tb = n0 - HALO;

    // q tile: rows [n0, n0+64)
    for (int idx = tid; idx < RB * 16; idx += 256) {
        int r = idx >> 4, c = (idx & 15) << 2;
        float4 v = *reinterpret_cast<const float4*>(
            &g_qkv[((size_t)(b * N_) + n0 + r) * QKV_N + h * Dh_ + c]);
        qs[r][c] = v.x; qs[r][c+1] = v.y; qs[r][c+2] = v.z; qs[r][c+3] = v.w;
    }
    // k tile: rows [tb, tb+104) clipped
    for (int idx = tid; idx < TR * 16; idx += 256) {
        int r = idx >> 4, c = (idx & 15) << 2;
        int gr = tb + r;
        float4 v = make_float4(0.f, 0.f, 0.f, 0.f);
        if (gr >= 0 && gr < N_)
            v = *reinterpret_cast<const float4*>(
                &g_qkv[((size_t)(b * N_) + gr) * QKV_N + C_ + h * Dh_ + c]);
        ks[r][c] = v.x; ks[r][c+1] = v.y; ks[r][c+2] = v.z; ks[r][c+3] = v.w;
    }
    __syncthreads();

    const int warp = tid >> 5, lane = tid & 31;
    const float* vrow = g_qkv + (size_t)(b * N_) * QKV_N + 2 * C_ + h * Dh_;

    for (int rr = warp; rr < RB; rr += 8) {
        const int n   = n0 + rr;
        const int mlo = max(0, n - w);
        const int mhi = min(N_ - 1, n + w);
        const int nb  = mhi - mlo + 1;          // <= 41

        const int  j0 = lane, j1 = lane + 32;
        const bool v0 = (j0 < nb), v1 = (j1 < nb);
        const int  tr0 = v0 ? (mlo - tb + j0) : 0;
        const int  tr1 = v1 ? (mlo - tb + j1) : 0;

        float s0 = 0.f, s1 = 0.f;
        #pragma unroll 8
        for (int d = 0; d < Dh_; d++) {
            float qd = qs[rr][d];
            s0 = fmaf(qd, ks[tr0][d], s0);
            s1 = fmaf(qd, ks[tr1][d], s1);
        }
        float l0 = v0 ? s0 * 4.0f : -3.4e38f;   // scale = Dh//H = 4
        float l1 = v1 ? s1 * 4.0f : -3.4e38f;

        float lm = fmaxf(l0, l1);
        #pragma unroll
        for (int o = 16; o > 0; o >>= 1)
            lm = fmaxf(lm, __shfl_xor_sync(0xffffffffu, lm, o));
        lm = fmaxf(lm, 1e-9f);                  // masked logits participate in max

        float e0 = v0 ? __expf(l0 - lm) : 0.f;
        float e1 = v1 ? __expf(l1 - lm) : 0.f;
        float ssum = e0 + e1;
        #pragma unroll
        for (int o = 16; o > 0; o >>= 1)
            ssum += __shfl_xor_sync(0xffffffffu, ssum, o);

        float c0   = __expf(1e-9f - lm);        // weight of every masked position
        float Z    = ssum + (float)(N_ - nb) * c0;
        float invZ = 1.0f / Z;

        ew[warp][j0] = e0;
        ew[warp][j1] = e1;
        __syncwarp();

        const int d0 = lane, d1 = lane + 32;
        float a0 = c0 * vsum_s[d0];             // out-of-band contribution
        float a1 = c0 * vsum_s[d1];
        const float* vb = vrow + (size_t)mlo * QKV_N;
        #pragma unroll 2
        for (int j = 0; j < nb; j++) {
            float em = ew[warp][j] - c0;        // replace band's c0 share with e_m
            a0 = fmaf(em, vb[(size_t)j * QKV_N + d0], a0);
            a1 = fmaf(em, vb[(size_t)j * QKV_N + d1], a1);
        }
        const size_t orow = ((size_t)(b * N_) + n) * C_ + h * Dh_;
        g_ao[orow + d0] = a0 * invZ;
        g_ao[orow + d1] = a1 * invZ;
        __syncwarp();
    }
}

// ---------------------------------------------------------------------------
extern "C" void kernel_launch(void* const* d_in, const int* in_sizes, int n_in,
                              void* d_out, int out_size)
{
    const float* x      = (const float*)d_in[0];
    const float* qkv_w  = (const float*)d_in[1];
    const float* proj_w = (const float*)d_in[2];
    const float* proj_b = (const float*)d_in[3];
    const int*   epoch  = (const int*)  d_in[4];
    float*       out    = (float*)d_out;

    float *qkv_p = nullptr, *ao_p = nullptr;
    cudaGetSymbolAddress((void**)&qkv_p, g_qkv);
    cudaGetSymbolAddress((void**)&ao_p,  g_ao);

    // 1) QKV GEMM: [4096,3072] = x[4096,1024] @ qkv_w[3072,1024]^T
    dim3 g1(QKV_N / 128, M_ROWS / 128);
    sgemm_tn<false><<<g1, 256>>>(x, qkv_w, nullptr, qkv_p, M_ROWS, QKV_N, C_);

    // 2) Per-(b,h) V column sums
    vsum_kernel<<<B_ * H_, 1024>>>();

    // 3) Banded attention with exact 1e-9 mask semantics
    attn_kernel<<<dim3(N_ / 64, H_, B_), 256>>>(epoch);

    // 4) Output projection: out[4096,1024] = ao @ proj_w^T + proj_b
    dim3 g2(C_ / 128, M_ROWS / 128);
    sgemm_tn<true><<<g2, 256>>>(ao_p, proj_w, proj_b, out, M_ROWS, C_, C_);
}

// round 9
// speedup vs baseline: 2.2816x; 2.2816x over previous
#include <cuda_runtime.h>
#include <cuda_bf16.h>
#include <cstdint>

// Fixed problem shapes.
constexpr int B_   = 2;
constexpr int N_   = 2048;
constexpr int C_   = 1024;
constexpr int H_   = 16;
constexpr int Dh_  = 64;
constexpr int MR   = B_ * N_;      // 4096
constexpr int QKVN = 3 * C_;       // 3072
constexpr int K_   = 1024;

// ---------------- device scratch (no allocs allowed) ----------------
__device__ float g_qkv[(size_t)MR * QKVN];     // fp32 qkv (attention reads this)
__device__ float g_vsum[B_ * H_ * Dh_];

__device__ __nv_bfloat16 g_xh[(size_t)MR * K_],   g_xm[(size_t)MR * K_];
__device__ __nv_bfloat16 g_wh[(size_t)QKVN * K_], g_wm[(size_t)QKVN * K_];
__device__ __nv_bfloat16 g_ph[(size_t)C_ * K_],   g_pl[(size_t)C_ * K_];
__device__ __nv_bfloat16 g_aoh[(size_t)MR * C_],  g_aol[(size_t)MR * C_];

// ---------------- helpers ----------------
__device__ __forceinline__ uint32_t smem_u32(const void* p) {
    uint32_t a;
    asm("{ .reg .u64 t; cvta.to.shared.u64 t, %1; cvt.u32.u64 %0, t; }" : "=r"(a) : "l"(p));
    return a;
}
__device__ __forceinline__ uint32_t sw128(uint32_t o) { return o ^ ((o >> 3) & 0x70); }

__device__ __forceinline__ void cp_async16(uint32_t dst, const void* src) {
    asm volatile("cp.async.cg.shared.global [%0], [%1], 16;" :: "r"(dst), "l"(src));
}
__device__ __forceinline__ void cp_commit() {
    asm volatile("cp.async.commit_group;" ::: "memory");
}
template<int Np> __device__ __forceinline__ void cp_wait() {
    asm volatile("cp.async.wait_group %0;" :: "n"(Np) : "memory");
}
__device__ __forceinline__ void ldsm_x4(uint32_t addr, uint32_t& r0, uint32_t& r1,
                                        uint32_t& r2, uint32_t& r3) {
    asm volatile("ldmatrix.sync.aligned.m8n8.x4.shared.b16 {%0,%1,%2,%3}, [%4];"
                 : "=r"(r0), "=r"(r1), "=r"(r2), "=r"(r3) : "r"(addr));
}
__device__ __forceinline__ void mma_bf16(float* d, const uint32_t* a, const uint32_t* b) {
    asm volatile(
        "mma.sync.aligned.m16n8k16.row.col.f32.bf16.bf16.f32 "
        "{%0,%1,%2,%3}, {%4,%5,%6,%7}, {%8,%9}, {%0,%1,%2,%3};"
        : "+f"(d[0]), "+f"(d[1]), "+f"(d[2]), "+f"(d[3])
        : "r"(a[0]), "r"(a[1]), "r"(a[2]), "r"(a[3]), "r"(b[0]), "r"(b[1]));
}

// ---------------- exact 2-limb bf16 split ----------------
__global__ void split2_kernel(const float* __restrict__ in,
                              __nv_bfloat16* __restrict__ h,
                              __nv_bfloat16* __restrict__ l, int n4) {
    int i = blockIdx.x * blockDim.x + threadIdx.x;
    if (i >= n4) return;
    float4 v = reinterpret_cast<const float4*>(in)[i];
    float xv[4] = {v.x, v.y, v.z, v.w};
    __nv_bfloat16 hh[4], ll[4];
#pragma unroll
    for (int j = 0; j < 4; j++) {
        float x = xv[j];
        __nv_bfloat16 a = __float2bfloat16(x);
        float r = x - __bfloat162float(a);
        hh[j] = a; ll[j] = __float2bfloat16(r);
    }
    reinterpret_cast<__nv_bfloat162*>(h)[2*i]   = __halves2bfloat162(hh[0], hh[1]);
    reinterpret_cast<__nv_bfloat162*>(h)[2*i+1] = __halves2bfloat162(hh[2], hh[3]);
    reinterpret_cast<__nv_bfloat162*>(l)[2*i]   = __halves2bfloat162(ll[0], ll[1]);
    reinterpret_cast<__nv_bfloat162*>(l)[2*i+1] = __halves2bfloat162(ll[2], ll[3]);
}

// ---------------- multi-pass bf16 HMMA GEMM ----------------
// D[MR,Nn] = sum_p A_p[MR,K] @ B_p[Nn,K]^T (+bias). 128x128 tile, BK=64,
// 8 warps (4m x 2n), cp.async double buffer, SW128 swizzled SMEM.
struct Passes { const __nv_bfloat16* a[3]; const __nv_bfloat16* b[3]; };

constexpr int SMEM_STAGE = 32768;                  // 16KB A + 16KB B
constexpr int SMEM_GEMM_TOTAL = 2 * SMEM_STAGE;    // 64KB

__device__ __forceinline__ void load_chunk(const Passes& pp, int c, uint32_t sbase,
                                           int s, int bm, int bn, int tid) {
    const int p = c >> 4, kc = c & 15;
    const __nv_bfloat16* __restrict__ A  = pp.a[p];
    const __nv_bfloat16* __restrict__ Bw = pp.b[p];
    const int k0 = kc * 64;
    const uint32_t sa = sbase + s * SMEM_STAGE;
    const uint32_t sb = sa + 16384;
#pragma unroll
    for (int i = 0; i < 4; i++) {
        int idx = tid + i * 256;           // 0..1023
        int r = idx >> 3, ch = idx & 7;    // row 0..127, 16B chunk 0..7
        cp_async16(sa + sw128(r * 128 + ch * 16),
                   A + (size_t)(bm + r) * K_ + k0 + ch * 8);
        cp_async16(sb + sw128(r * 128 + ch * 16),
                   Bw + (size_t)(bn + r) * K_ + k0 + ch * 8);
    }
}

template<int NPASS, bool BIAS>
__global__ __launch_bounds__(256, 1) void hgemm(Passes pp, const float* __restrict__ bias,
                                                float* __restrict__ D, int Nn) {
    extern __shared__ char smem[];
    const uint32_t sbase = smem_u32(smem);
    const int tid = threadIdx.x;
    const int warp = tid >> 5, lane = tid & 31;
    const int bm = blockIdx.y * 128, bn = blockIdx.x * 128;
    const int wm = (warp >> 1) * 32;   // warp m-offset (4 warps)
    const int wn = (warp & 1) * 64;    // warp n-offset (2 warps)

    float acc[2][8][4];
#pragma unroll
    for (int t = 0; t < 2; t++)
#pragma unroll
        for (int j = 0; j < 8; j++)
#pragma unroll
            for (int q = 0; q < 4; q++) acc[t][j][q] = 0.f;

    constexpr int CHUNKS = NPASS * (K_ / 64);

    load_chunk(pp, 0, sbase, 0, bm, bn, tid); cp_commit();
    load_chunk(pp, 1, sbase, 1, bm, bn, tid); cp_commit();

    for (int c = 0; c < CHUNKS; c++) {
        if (c + 1 < CHUNKS) cp_wait<1>(); else cp_wait<0>();
        __syncthreads();

        const uint32_t sa = sbase + (c & 1) * SMEM_STAGE;
        const uint32_t sb = sa + 16384;
        const int lrow = lane & 15;
        const int lcol = (lane >> 4) * 16;
#pragma unroll
        for (int kk = 0; kk < 4; kk++) {
            const int kb = kk * 32;
            uint32_t af[2][4];
#pragma unroll
            for (int t = 0; t < 2; t++) {
                uint32_t addr = sa + sw128((wm + t * 16 + lrow) * 128 + kb + lcol);
                ldsm_x4(addr, af[t][0], af[t][1], af[t][2], af[t][3]);
            }
            uint32_t bf[8][2];
#pragma unroll
            for (int u = 0; u < 4; u++) {
                uint32_t addr = sb + sw128((wn + u * 16 + lrow) * 128 + kb + lcol);
                uint32_t b0, b1, b2, b3;
                ldsm_x4(addr, b0, b1, b2, b3);
                bf[2*u][0] = b0; bf[2*u][1] = b2;       // n-rows 0-7 of this n16
                bf[2*u+1][0] = b1; bf[2*u+1][1] = b3;   // n-rows 8-15
            }
#pragma unroll
            for (int t = 0; t < 2; t++)
#pragma unroll
                for (int j = 0; j < 8; j++)
                    mma_bf16(acc[t][j], af[t], bf[j]);
        }
        __syncthreads();
        if (c + 2 < CHUNKS) { load_chunk(pp, c + 2, sbase, c & 1, bm, bn, tid); cp_commit(); }
    }

    // Epilogue: D frag thread map — rows l/4 & l/4+8, cols (l%4)*2..+1.
    const int r0 = lane >> 2, c2 = (lane & 3) * 2;
#pragma unroll
    for (int t = 0; t < 2; t++) {
        const int row = bm + wm + t * 16 + r0;
#pragma unroll
        for (int j = 0; j < 8; j++) {
            const int col = bn + wn + j * 8 + c2;
            float bx = 0.f, by = 0.f;
            if (BIAS) { bx = bias[col]; by = bias[col + 1]; }
            float2 v0 = make_float2(acc[t][j][0] + bx, acc[t][j][1] + by);
            float2 v1 = make_float2(acc[t][j][2] + bx, acc[t][j][3] + by);
            *reinterpret_cast<float2*>(&D[(size_t)row * Nn + col]) = v0;
            *reinterpret_cast<float2*>(&D[(size_t)(row + 8) * Nn + col]) = v1;
        }
    }
}

// ---------------- Vsum ----------------
__global__ __launch_bounds__(1024) void vsum_kernel() {
    const int bh = blockIdx.x, tid = threadIdx.x;
    const int d = tid & 63, part = tid >> 6;
    const int b = bh >> 4, h = bh & 15;
    const float* vp = g_qkv + (size_t)(b * N_) * QKVN + 2 * C_ + h * Dh_ + d;
    const int n0 = part * 128;
    float s0 = 0.f, s1 = 0.f, s2 = 0.f, s3 = 0.f;
    for (int n = 0; n < 128; n += 4) {
        s0 += vp[(size_t)(n0 + n    ) * QKVN];
        s1 += vp[(size_t)(n0 + n + 1) * QKVN];
        s2 += vp[(size_t)(n0 + n + 2) * QKVN];
        s3 += vp[(size_t)(n0 + n + 3) * QKVN];
    }
    __shared__ float red[1024];
    red[tid] = (s0 + s1) + (s2 + s3);
    __syncthreads();
    if (part == 0) {
        float s = 0.f;
#pragma unroll
        for (int p = 0; p < 16; p++) s += red[p * 64 + d];
        g_vsum[bh * 64 + d] = s;
    }
}

// ---------------- Banded attention (exact 1e-9 mask), emits hi/lo bf16 ----------------
__global__ __launch_bounds__(256) void attn_kernel(const int* __restrict__ epoch) {
    constexpr int RB = 64, HALO = 20, TR = RB + 2 * HALO, LD = 65;
    const int b = blockIdx.z, h = blockIdx.y, n0 = blockIdx.x * RB;
    const int w = (*epoch < 15) ? 16 : 20;

    __shared__ float qs[RB][LD];
    __shared__ float ks[TR][LD];
    __shared__ float ew[8][64];
    __shared__ float vsum_s[64];

    const int tid = threadIdx.x;
    if (tid < 64) vsum_s[tid] = g_vsum[(b * H_ + h) * 64 + tid];
    const int tb = n0 - HALO;

    for (int idx = tid; idx < RB * 16; idx += 256) {
        int r = idx >> 4, c = (idx & 15) << 2;
        float4 v = *reinterpret_cast<const float4*>(
            &g_qkv[((size_t)(b * N_) + n0 + r) * QKVN + h * Dh_ + c]);
        qs[r][c] = v.x; qs[r][c+1] = v.y; qs[r][c+2] = v.z; qs[r][c+3] = v.w;
    }
    for (int idx = tid; idx < TR * 16; idx += 256) {
        int r = idx >> 4, c = (idx & 15) << 2;
        int gr = tb + r;
        float4 v = make_float4(0.f, 0.f, 0.f, 0.f);
        if (gr >= 0 && gr < N_)
            v = *reinterpret_cast<const float4*>(
                &g_qkv[((size_t)(b * N_) + gr) * QKVN + C_ + h * Dh_ + c]);
        ks[r][c] = v.x; ks[r][c+1] = v.y; ks[r][c+2] = v.z; ks[r][c+3] = v.w;
    }
    __syncthreads();

    const int warp = tid >> 5, lane = tid & 31;
    const float* vrow = g_qkv + (size_t)(b * N_) * QKVN + 2 * C_ + h * Dh_;

    for (int rr = warp; rr < RB; rr += 8) {
        const int n = n0 + rr;
        const int mlo = max(0, n - w);
        const int mhi = min(N_ - 1, n + w);
        const int nb = mhi - mlo + 1;

        const int j0 = lane, j1 = lane + 32;
        const bool v0 = (j0 < nb), v1 = (j1 < nb);
        const int tr0 = v0 ? (mlo - tb + j0) : 0;
        const int tr1 = v1 ? (mlo - tb + j1) : 0;

        float s0 = 0.f, s1 = 0.f;
#pragma unroll 8
        for (int d = 0; d < Dh_; d++) {
            float qd = qs[rr][d];
            s0 = fmaf(qd, ks[tr0][d], s0);
            s1 = fmaf(qd, ks[tr1][d], s1);
        }
        float l0 = v0 ? s0 * 4.0f : -3.4e38f;   // scale = Dh // H = 4
        float l1 = v1 ? s1 * 4.0f : -3.4e38f;

        float lm = fmaxf(l0, l1);
#pragma unroll
        for (int o = 16; o > 0; o >>= 1)
            lm = fmaxf(lm, __shfl_xor_sync(0xffffffffu, lm, o));
        lm = fmaxf(lm, 1e-9f);

        float e0 = v0 ? __expf(l0 - lm) : 0.f;
        float e1 = v1 ? __expf(l1 - lm) : 0.f;
        float ssum = e0 + e1;
#pragma unroll
        for (int o = 16; o > 0; o >>= 1)
            ssum += __shfl_xor_sync(0xffffffffu, ssum, o);

        float c0 = __expf(1e-9f - lm);
        float Z = ssum + (float)(N_ - nb) * c0;
        float invZ = 1.0f / Z;

        ew[warp][j0] = e0;
        ew[warp][j1] = e1;
        __syncwarp();

        const int d0 = lane, d1 = lane + 32;
        float a0 = c0 * vsum_s[d0];
        float a1 = c0 * vsum_s[d1];
        const float* vb = vrow + (size_t)mlo * QKVN;
#pragma unroll 2
        for (int j = 0; j < nb; j++) {
            float em = ew[warp][j] - c0;
            a0 = fmaf(em, vb[(size_t)j * QKVN + d0], a0);
            a1 = fmaf(em, vb[(size_t)j * QKVN + d1], a1);
        }
        const size_t orow = ((size_t)(b * N_) + n) * C_ + h * Dh_;
        float o0 = a0 * invZ, o1 = a1 * invZ;
        __nv_bfloat16 h0 = __float2bfloat16(o0);
        __nv_bfloat16 h1 = __float2bfloat16(o1);
        g_aoh[orow + d0] = h0;
        g_aoh[orow + d1] = h1;
        g_aol[orow + d0] = __float2bfloat16(o0 - __bfloat162float(h0));
        g_aol[orow + d1] = __float2bfloat16(o1 - __bfloat162float(h1));
        __syncwarp();
    }
}

// ---------------- launch ----------------
extern "C" void kernel_launch(void* const* d_in, const int* in_sizes, int n_in,
                              void* d_out, int out_size) {
    const float* x      = (const float*)d_in[0];
    const float* qkv_w  = (const float*)d_in[1];
    const float* proj_w = (const float*)d_in[2];
    const float* proj_b = (const float*)d_in[3];
    const int*   epoch  = (const int*)  d_in[4];
    float*       out    = (float*)d_out;

    float* qkv_p = nullptr;
    __nv_bfloat16 *xh, *xm, *wh, *wm, *ph, *pl, *aoh, *aol;
    cudaGetSymbolAddress((void**)&qkv_p, g_qkv);
    cudaGetSymbolAddress((void**)&xh, g_xh);   cudaGetSymbolAddress((void**)&xm, g_xm);
    cudaGetSymbolAddress((void**)&wh, g_wh);   cudaGetSymbolAddress((void**)&wm, g_wm);
    cudaGetSymbolAddress((void**)&ph, g_ph);   cudaGetSymbolAddress((void**)&pl, g_pl);
    cudaGetSymbolAddress((void**)&aoh, g_aoh); cudaGetSymbolAddress((void**)&aol, g_aol);

    cudaFuncSetAttribute(hgemm<3, false>, cudaFuncAttributeMaxDynamicSharedMemorySize,
                         SMEM_GEMM_TOTAL);
    cudaFuncSetAttribute(hgemm<3, true>, cudaFuncAttributeMaxDynamicSharedMemorySize,
                         SMEM_GEMM_TOTAL);

    // 0) exact 2-limb bf16 splits
    {
        int n4 = MR * K_ / 4;
        split2_kernel<<<(n4 + 255) / 256, 256>>>(x, xh, xm, n4);
        n4 = QKVN * K_ / 4;
        split2_kernel<<<(n4 + 255) / 256, 256>>>(qkv_w, wh, wm, n4);
        n4 = C_ * K_ / 4;
        split2_kernel<<<(n4 + 255) / 256, 256>>>(proj_w, ph, pl, n4);
    }

    // 1) QKV GEMM, 3-pass (hh + hm + mh): g_qkv = x @ qkv_w^T
    {
        Passes p{};
        p.a[0] = xh; p.b[0] = wh;
        p.a[1] = xh; p.b[1] = wm;
        p.a[2] = xm; p.b[2] = wh;
        hgemm<3, false><<<dim3(QKVN / 128, MR / 128), 256, SMEM_GEMM_TOTAL>>>(
            p, nullptr, qkv_p, QKVN);
    }

    // 2) per-(b,h) V column sums
    vsum_kernel<<<B_ * H_, 1024>>>();

    // 3) banded attention with exact 1e-9 mask semantics (emits bf16 hi/lo)
    attn_kernel<<<dim3(N_ / 64, H_, B_), 256>>>(epoch);

    // 4) projection GEMM, 3-pass: out = ao @ proj_w^T + bias
    {
        Passes p{};
        p.a[0] = aoh; p.b[0] = ph;
        p.a[1] = aoh; p.b[1] = pl;
        p.a[2] = aol; p.b[2] = ph;
        hgemm<3, true><<<dim3(C_ / 128, MR / 128), 256, SMEM_GEMM_TOTAL>>>(
            p, proj_b, out, C_);
    }
}

// round 12
// speedup vs baseline: 2.5020x; 1.0966x over previous
#include <cuda_runtime.h>
#include <cuda_bf16.h>
#include <cstdint>

// Fixed problem shapes.
constexpr int B_   = 2;
constexpr int N_   = 2048;
constexpr int C_   = 1024;
constexpr int H_   = 16;
constexpr int Dh_  = 64;
constexpr int MR   = B_ * N_;      // 4096
constexpr int QKVN = 3 * C_;       // 3072
constexpr int K_   = 1024;

// ---------------- device scratch (no allocs allowed) ----------------
__device__ float g_qkv[(size_t)MR * QKVN];
__device__ float g_vsum[B_ * H_ * Dh_];

__device__ __nv_bfloat16 g_xh[(size_t)MR * K_],   g_xm[(size_t)MR * K_];
__device__ __nv_bfloat16 g_wh[(size_t)QKVN * K_], g_wm[(size_t)QKVN * K_];
__device__ __nv_bfloat16 g_ph[(size_t)C_ * K_],   g_pl[(size_t)C_ * K_];
__device__ __nv_bfloat16 g_aoh[(size_t)MR * C_],  g_aol[(size_t)MR * C_];

// ---------------- helpers ----------------
__device__ __forceinline__ uint32_t smem_u32(const void* p) {
    uint32_t a;
    asm("{ .reg .u64 t; cvta.to.shared.u64 t, %1; cvt.u32.u64 %0, t; }" : "=r"(a) : "l"(p));
    return a;
}
__device__ __forceinline__ uint32_t sw128(uint32_t o) { return o ^ ((o >> 3) & 0x70); }

__device__ __forceinline__ void cp_async16(uint32_t dst, const void* src) {
    asm volatile("cp.async.cg.shared.global [%0], [%1], 16;" :: "r"(dst), "l"(src));
}
__device__ __forceinline__ void cp_commit() {
    asm volatile("cp.async.commit_group;" ::: "memory");
}
template<int Np> __device__ __forceinline__ void cp_wait() {
    asm volatile("cp.async.wait_group %0;" :: "n"(Np) : "memory");
}
__device__ __forceinline__ void ldsm_x4(uint32_t addr, uint32_t& r0, uint32_t& r1,
                                        uint32_t& r2, uint32_t& r3) {
    asm volatile("ldmatrix.sync.aligned.m8n8.x4.shared.b16 {%0,%1,%2,%3}, [%4];"
                 : "=r"(r0), "=r"(r1), "=r"(r2), "=r"(r3) : "r"(addr));
}
__device__ __forceinline__ void mma_bf16(float* d, const uint32_t* a, const uint32_t* b) {
    asm volatile(
        "mma.sync.aligned.m16n8k16.row.col.f32.bf16.bf16.f32 "
        "{%0,%1,%2,%3}, {%4,%5,%6,%7}, {%8,%9}, {%0,%1,%2,%3};"
        : "+f"(d[0]), "+f"(d[1]), "+f"(d[2]), "+f"(d[3])
        : "r"(a[0]), "r"(a[1]), "r"(a[2]), "r"(a[3]), "r"(b[0]), "r"(b[1]));
}

// ---------------- exact 2-limb bf16 split ----------------
__global__ void split2_kernel(const float* __restrict__ in,
                              __nv_bfloat16* __restrict__ h,
                              __nv_bfloat16* __restrict__ l, int n4) {
    int i = blockIdx.x * blockDim.x + threadIdx.x;
    if (i >= n4) return;
    float4 v = reinterpret_cast<const float4*>(in)[i];
    float xv[4] = {v.x, v.y, v.z, v.w};
    __nv_bfloat16 hh[4], ll[4];
#pragma unroll
    for (int j = 0; j < 4; j++) {
        float x = xv[j];
        __nv_bfloat16 a = __float2bfloat16(x);
        float r = x - __bfloat162float(a);
        hh[j] = a; ll[j] = __float2bfloat16(r);
    }
    reinterpret_cast<__nv_bfloat162*>(h)[2*i]   = __halves2bfloat162(hh[0], hh[1]);
    reinterpret_cast<__nv_bfloat162*>(h)[2*i+1] = __halves2bfloat162(hh[2], hh[3]);
    reinterpret_cast<__nv_bfloat162*>(l)[2*i]   = __halves2bfloat162(ll[0], ll[1]);
    reinterpret_cast<__nv_bfloat162*>(l)[2*i+1] = __halves2bfloat162(ll[2], ll[3]);
}

// ---------------- multi-pass bf16 HMMA GEMM ----------------
// D[MR,Nn] = sum_p A_p[MR,K] @ B_p[Nn,K]^T (+bias). 128x128 tile, BK=64,
// 8 warps (4m x 2n), 3-stage cp.async ring, SW128 swizzled SMEM, 2 CTAs/SM.
struct Passes { const __nv_bfloat16* a[3]; const __nv_bfloat16* b[3]; };

constexpr int SMEM_STAGE = 32768;                  // 16KB A + 16KB B
constexpr int NSTAGE = 3;
constexpr int SMEM_GEMM_TOTAL = NSTAGE * SMEM_STAGE;   // 96KB

__device__ __forceinline__ void load_chunk(const Passes& pp, int c, uint32_t sbase,
                                           int s, int bm, int bn, int tid) {
    const int p = c >> 4, kc = c & 15;
    const __nv_bfloat16* __restrict__ A  = pp.a[p];
    const __nv_bfloat16* __restrict__ Bw = pp.b[p];
    const int k0 = kc * 64;
    const uint32_t sa = sbase + s * SMEM_STAGE;
    const uint32_t sb = sa + 16384;
#pragma unroll
    for (int i = 0; i < 4; i++) {
        int idx = tid + i * 256;           // 0..1023
        int r = idx >> 3, ch = idx & 7;    // row 0..127, 16B chunk 0..7
        cp_async16(sa + sw128(r * 128 + ch * 16),
                   A + (size_t)(bm + r) * K_ + k0 + ch * 8);
        cp_async16(sb + sw128(r * 128 + ch * 16),
                   Bw + (size_t)(bn + r) * K_ + k0 + ch * 8);
    }
}

template<int NPASS, bool BIAS>
__global__ __launch_bounds__(256, 2) void hgemm(Passes pp, const float* __restrict__ bias,
                                                float* __restrict__ D, int Nn) {
    extern __shared__ char smem[];
    const uint32_t sbase = smem_u32(smem);
    const int tid = threadIdx.x;
    const int warp = tid >> 5, lane = tid & 31;
    const int bm = blockIdx.y * 128, bn = blockIdx.x * 128;
    const int wm = (warp >> 1) * 32;   // warp m-offset (4 warps)
    const int wn = (warp & 1) * 64;    // warp n-offset (2 warps)

    float acc[2][8][4];
#pragma unroll
    for (int t = 0; t < 2; t++)
#pragma unroll
        for (int j = 0; j < 8; j++)
#pragma unroll
            for (int q = 0; q < 4; q++) acc[t][j][q] = 0.f;

    constexpr int CHUNKS = NPASS * (K_ / 64);

    load_chunk(pp, 0, sbase, 0, bm, bn, tid); cp_commit();
    load_chunk(pp, 1, sbase, 1, bm, bn, tid); cp_commit();

    int s_cur = 0, s_load = 2;
    const int lrow = lane & 15;
    const int lcol = (lane >> 4) * 16;

    for (int c = 0; c < CHUNKS; c++) {
        if (c + 1 < CHUNKS) cp_wait<1>(); else cp_wait<0>();
        __syncthreads();   // all warps done with stage s_load's previous contents

        const uint32_t sa = sbase + s_cur * SMEM_STAGE;
        const uint32_t sb = sa + 16384;
#pragma unroll
        for (int kk = 0; kk < 4; kk++) {
            const int kb = kk * 32;
            uint32_t af[2][4];
#pragma unroll
            for (int t = 0; t < 2; t++) {
                uint32_t addr = sa + sw128((wm + t * 16 + lrow) * 128 + kb + lcol);
                ldsm_x4(addr, af[t][0], af[t][1], af[t][2], af[t][3]);
            }
            uint32_t bf[8][2];
#pragma unroll
            for (int u = 0; u < 4; u++) {
                uint32_t addr = sb + sw128((wn + u * 16 + lrow) * 128 + kb + lcol);
                uint32_t b0, b1, b2, b3;
                ldsm_x4(addr, b0, b1, b2, b3);
                bf[2*u][0] = b0;   bf[2*u][1] = b2;
                bf[2*u+1][0] = b1; bf[2*u+1][1] = b3;
            }
#pragma unroll
            for (int t = 0; t < 2; t++)
#pragma unroll
                for (int j = 0; j < 8; j++)
                    mma_bf16(acc[t][j], af[t], bf[j]);
        }
        if (c + 2 < CHUNKS) {
            load_chunk(pp, c + 2, sbase, s_load, bm, bn, tid);
            cp_commit();
        }
        s_cur  = (s_cur  == NSTAGE - 1) ? 0 : s_cur + 1;
        s_load = (s_load == NSTAGE - 1) ? 0 : s_load + 1;
    }

    // Epilogue: rows l/4 & l/4+8, cols (l%4)*2..+1 per n8 frag.
    const int r0 = lane >> 2, c2 = (lane & 3) * 2;
#pragma unroll
    for (int t = 0; t < 2; t++) {
        const int row = bm + wm + t * 16 + r0;
#pragma unroll
        for (int j = 0; j < 8; j++) {
            const int col = bn + wn + j * 8 + c2;
            float bx = 0.f, by = 0.f;
            if (BIAS) { bx = bias[col]; by = bias[col + 1]; }
            float2 v0 = make_float2(acc[t][j][0] + bx, acc[t][j][1] + by);
            float2 v1 = make_float2(acc[t][j][2] + bx, acc[t][j][3] + by);
            *reinterpret_cast<float2*>(&D[(size_t)row * Nn + col]) = v0;
            *reinterpret_cast<float2*>(&D[(size_t)(row + 8) * Nn + col]) = v1;
        }
    }
}

// ---------------- Vsum ----------------
__global__ __launch_bounds__(1024) void vsum_kernel() {
    const int bh = blockIdx.x, tid = threadIdx.x;
    const int d = tid & 63, part = tid >> 6;
    const int b = bh >> 4, h = bh & 15;
    const float* vp = g_qkv + (size_t)(b * N_) * QKVN + 2 * C_ + h * Dh_ + d;
    const int n0 = part * 128;
    float s0 = 0.f, s1 = 0.f, s2 = 0.f, s3 = 0.f;
    for (int n = 0; n < 128; n += 4) {
        s0 += vp[(size_t)(n0 + n    ) * QKVN];
        s1 += vp[(size_t)(n0 + n + 1) * QKVN];
        s2 += vp[(size_t)(n0 + n + 2) * QKVN];
        s3 += vp[(size_t)(n0 + n + 3) * QKVN];
    }
    __shared__ float red[1024];
    red[tid] = (s0 + s1) + (s2 + s3);
    __syncthreads();
    if (part == 0) {
        float s = 0.f;
#pragma unroll
        for (int p = 0; p < 16; p++) s += red[p * 64 + d];
        g_vsum[bh * 64 + d] = s;
    }
}

// ---------------- Banded attention (exact 1e-9 mask), emits hi/lo bf16 ----------------
__global__ __launch_bounds__(256) void attn_kernel(const int* __restrict__ epoch) {
    constexpr int RB = 64, HALO = 20, TR = RB + 2 * HALO, LD = 65;
    const int b = blockIdx.z, h = blockIdx.y, n0 = blockIdx.x * RB;
    const int w = (*epoch < 15) ? 16 : 20;

    __shared__ float qs[RB][LD];
    __shared__ float ks[TR][LD];
    __shared__ float ew[8][64];
    __shared__ float vsum_s[64];

    const int tid = threadIdx.x;
    if (tid < 64) vsum_s[tid] = g_vsum[(b * H_ + h) * 64 + tid];
    const int tb = n0 - HALO;

    for (int idx = tid; idx < RB * 16; idx += 256) {
        int r = idx >> 4, c = (idx & 15) << 2;
        float4 v = *reinterpret_cast<const float4*>(
            &g_qkv[((size_t)(b * N_) + n0 + r) * QKVN + h * Dh_ + c]);
        qs[r][c] = v.x; qs[r][c+1] = v.y; qs[r][c+2] = v.z; qs[r][c+3] = v.w;
    }
    for (int idx = tid; idx < TR * 16; idx += 256) {
        int r = idx >> 4, c = (idx & 15) << 2;
        int gr = tb + r;
        float4 v = make_float4(0.f, 0.f, 0.f, 0.f);
        if (gr >= 0 && gr < N_)
            v = *reinterpret_cast<const float4*>(
                &g_qkv[((size_t)(b * N_) + gr) * QKVN + C_ + h * Dh_ + c]);
        ks[r][c] = v.x; ks[r][c+1] = v.y; ks[r][c+2] = v.z; ks[r][c+3] = v.w;
    }
    __syncthreads();

    const int warp = tid >> 5, lane = tid & 31;
    const float* vrow = g_qkv + (size_t)(b * N_) * QKVN + 2 * C_ + h * Dh_;

    for (int rr = warp; rr < RB; rr += 8) {
        const int n = n0 + rr;
        const int mlo = max(0, n - w);
        const int mhi = min(N_ - 1, n + w);
        const int nb = mhi - mlo + 1;

        const int j0 = lane, j1 = lane + 32;
        const bool v0 = (j0 < nb), v1 = (j1 < nb);
        const int tr0 = v0 ? (mlo - tb + j0) : 0;
        const int tr1 = v1 ? (mlo - tb + j1) : 0;

        float s0 = 0.f, s1 = 0.f;
#pragma unroll 8
        for (int d = 0; d < Dh_; d++) {
            float qd = qs[rr][d];
            s0 = fmaf(qd, ks[tr0][d], s0);
            s1 = fmaf(qd, ks[tr1][d], s1);
        }
        float l0 = v0 ? s0 * 4.0f : -3.4e38f;   // scale = Dh // H = 4
        float l1 = v1 ? s1 * 4.0f : -3.4e38f;

        float lm = fmaxf(l0, l1);
#pragma unroll
        for (int o = 16; o > 0; o >>= 1)
            lm = fmaxf(lm, __shfl_xor_sync(0xffffffffu, lm, o));
        lm = fmaxf(lm, 1e-9f);

        float e0 = v0 ? __expf(l0 - lm) : 0.f;
        float e1 = v1 ? __expf(l1 - lm) : 0.f;
        float ssum = e0 + e1;
#pragma unroll
        for (int o = 16; o > 0; o >>= 1)
            ssum += __shfl_xor_sync(0xffffffffu, ssum, o);

        float c0 = __expf(1e-9f - lm);
        float Z = ssum + (float)(N_ - nb) * c0;
        float invZ = 1.0f / Z;

        ew[warp][j0] = e0;
        ew[warp][j1] = e1;
        __syncwarp();

        const int d0 = lane, d1 = lane + 32;
        float a0 = c0 * vsum_s[d0];
        float a1 = c0 * vsum_s[d1];
        const float* vb = vrow + (size_t)mlo * QKVN;
#pragma unroll 2
        for (int j = 0; j < nb; j++) {
            float em = ew[warp][j] - c0;
            a0 = fmaf(em, vb[(size_t)j * QKVN + d0], a0);
            a1 = fmaf(em, vb[(size_t)j * QKVN + d1], a1);
        }
        const size_t orow = ((size_t)(b * N_) + n) * C_ + h * Dh_;
        float o0 = a0 * invZ, o1 = a1 * invZ;
        __nv_bfloat16 h0 = __float2bfloat16(o0);
        __nv_bfloat16 h1 = __float2bfloat16(o1);
        g_aoh[orow + d0] = h0;
        g_aoh[orow + d1] = h1;
        g_aol[orow + d0] = __float2bfloat16(o0 - __bfloat162float(h0));
        g_aol[orow + d1] = __float2bfloat16(o1 - __bfloat162float(h1));
        __syncwarp();
    }
}

// ---------------- launch ----------------
extern "C" void kernel_launch(void* const* d_in, const int* in_sizes, int n_in,
                              void* d_out, int out_size) {
    const float* x      = (const float*)d_in[0];
    const float* qkv_w  = (const float*)d_in[1];
    const float* proj_w = (const float*)d_in[2];
    const float* proj_b = (const float*)d_in[3];
    const int*   epoch  = (const int*)  d_in[4];
    float*       out    = (float*)d_out;

    float* qkv_p = nullptr;
    __nv_bfloat16 *xh, *xm, *wh, *wm, *ph, *pl, *aoh, *aol;
    cudaGetSymbolAddress((void**)&qkv_p, g_qkv);
    cudaGetSymbolAddress((void**)&xh, g_xh);   cudaGetSymbolAddress((void**)&xm, g_xm);
    cudaGetSymbolAddress((void**)&wh, g_wh);   cudaGetSymbolAddress((void**)&wm, g_wm);
    cudaGetSymbolAddress((void**)&ph, g_ph);   cudaGetSymbolAddress((void**)&pl, g_pl);
    cudaGetSymbolAddress((void**)&aoh, g_aoh); cudaGetSymbolAddress((void**)&aol, g_aol);

    cudaFuncSetAttribute(hgemm<3, false>, cudaFuncAttributeMaxDynamicSharedMemorySize,
                         SMEM_GEMM_TOTAL);
    cudaFuncSetAttribute(hgemm<3, true>, cudaFuncAttributeMaxDynamicSharedMemorySize,
                         SMEM_GEMM_TOTAL);

    // 0) exact 2-limb bf16 splits
    {
        int n4 = MR * K_ / 4;
        split2_kernel<<<(n4 + 255) / 256, 256>>>(x, xh, xm, n4);
        n4 = QKVN * K_ / 4;
        split2_kernel<<<(n4 + 255) / 256, 256>>>(qkv_w, wh, wm, n4);
        n4 = C_ * K_ / 4;
        split2_kernel<<<(n4 + 255) / 256, 256>>>(proj_w, ph, pl, n4);
    }

    // 1) QKV GEMM, 3-pass (hh + hm + mh): g_qkv = x @ qkv_w^T
    {
        Passes p{};
        p.a[0] = xh; p.b[0] = wh;
        p.a[1] = xh; p.b[1] = wm;
        p.a[2] = xm; p.b[2] = wh;
        hgemm<3, false><<<dim3(QKVN / 128, MR / 128), 256, SMEM_GEMM_TOTAL>>>(
            p, nullptr, qkv_p, QKVN);
    }

    // 2) per-(b,h) V column sums
    vsum_kernel<<<B_ * H_, 1024>>>();

    // 3) banded attention with exact 1e-9 mask semantics (emits bf16 hi/lo)
    attn_kernel<<<dim3(N_ / 64, H_, B_), 256>>>(epoch);

    // 4) projection GEMM, 3-pass: out = ao @ proj_w^T + bias
    {
        Passes p{};
        p.a[0] = aoh; p.b[0] = ph;
        p.a[1] = aoh; p.b[1] = pl;
        p.a[2] = aol; p.b[2] = ph;
        hgemm<3, true><<<dim3(C_ / 128, MR / 128), 256, SMEM_GEMM_TOTAL>>>(
            p, proj_b, out, C_);
    }
}